// round 2
// baseline (speedup 1.0000x reference)
#include <cuda_runtime.h>
#include <cstdint>

#define B_ 2
#define H_ 16
#define S_ 2048
#define D_ 128
#define SCALE 0.08838834764831845f   // 1/sqrt(128)
#define NEG (-1e9f)

// ---------------------------------------------------------------------------
// Kernel 1: masked scaled scores  ->  attn region of d_out (used as scratch)
// Tile: 128 (queries) x 128 (keys), depth chunked by 32.
// 256 threads, each computes an 8x8 register tile split as 2x2 quadrants of 4
// so that LDS.128 reads are conflict-free.
// Tiles fully inside the sliding window (j0+128 <= floor(0.8*i0)) skip the
// GEMM and are filled with -1e9 (exp -> exactly 0 later).
// Mask arrives as int32 (bool promoted by the harness).
// ---------------------------------------------------------------------------
__global__ __launch_bounds__(256) void scores_kernel(
    const float* __restrict__ Q, const float* __restrict__ K,
    const int* __restrict__ mask, float* __restrict__ attn)
{
    const int bh = blockIdx.z;
    const int b  = bh >> 4;          // H_ = 16
    const int i0 = blockIdx.y * 128;
    const int j0 = blockIdx.x * 128;
    const int tid = threadIdx.x;
    const int tx = tid & 15;
    const int ty = tid >> 4;

    float* attnBase = attn + ((size_t)bh * S_ + i0) * S_ + j0;

    // Entire tile below the window threshold of every row in the tile?
    if (j0 + 128 <= (i0 * 4) / 5) {
        const float4 f = make_float4(NEG, NEG, NEG, NEG);
        for (int idx = tid; idx < 128 * 32; idx += 256) {
            int row = idx >> 5;
            int c4  = (idx & 31) << 2;
            *(float4*)&attnBase[(size_t)row * S_ + c4] = f;
        }
        return;
    }

    __shared__ float Qs[32][132];   // transposed: [k][m], padded stride
    __shared__ float Ks[32][132];   // transposed: [k][n]

    float acc[8][8];
    #pragma unroll
    for (int r = 0; r < 8; ++r)
        #pragma unroll
        for (int c = 0; c < 8; ++c) acc[r][c] = 0.0f;

    const float* Qb = Q + ((size_t)bh * S_ + i0) * D_;
    const float* Kb = K + ((size_t)bh * S_ + j0) * D_;

    const int lk  = tid & 31;   // k within chunk (coalesced gmem)
    const int lm0 = tid >> 5;   // row group 0..7

    for (int kc = 0; kc < D_; kc += 32) {
        __syncthreads();
        #pragma unroll
        for (int m = lm0; m < 128; m += 8) {
            Qs[lk][m] = Qb[(size_t)m * D_ + kc + lk];
            Ks[lk][m] = Kb[(size_t)m * D_ + kc + lk];
        }
        __syncthreads();

        #pragma unroll
        for (int k = 0; k < 32; ++k) {
            float qf[8], kf[8];
            float4 t;
            t = *(const float4*)&Qs[k][ty * 4];      qf[0]=t.x; qf[1]=t.y; qf[2]=t.z; qf[3]=t.w;
            t = *(const float4*)&Qs[k][64 + ty * 4]; qf[4]=t.x; qf[5]=t.y; qf[6]=t.z; qf[7]=t.w;
            t = *(const float4*)&Ks[k][tx * 4];      kf[0]=t.x; kf[1]=t.y; kf[2]=t.z; kf[3]=t.w;
            t = *(const float4*)&Ks[k][64 + tx * 4]; kf[4]=t.x; kf[5]=t.y; kf[6]=t.z; kf[7]=t.w;
            #pragma unroll
            for (int r = 0; r < 8; ++r)
                #pragma unroll
                for (int c = 0; c < 8; ++c)
                    acc[r][c] = fmaf(qf[r], kf[c], acc[r][c]);
        }
    }

    // Epilogue: scale + (random mask | sliding window) -> -1e9, write scores
    const int* mB = mask + (size_t)b * S_ * S_;
    #pragma unroll
    for (int rb = 0; rb < 2; ++rb)
        #pragma unroll
        for (int r = 0; r < 4; ++r) {
            int i   = i0 + rb * 64 + ty * 4 + r;
            int thr = (i * 4) / 5;
            const int* mrow = mB + (size_t)i * S_;
            float* orow = attn + ((size_t)bh * S_ + i) * S_;
            #pragma unroll
            for (int cb = 0; cb < 2; ++cb) {
                int j = j0 + cb * 64 + tx * 4;
                int4 mv = *(const int4*)&mrow[j];
                float4 v;
                v.x = (mv.x != 0 || (j + 0) < thr) ? NEG : acc[rb*4+r][cb*4+0] * SCALE;
                v.y = (mv.y != 0 || (j + 1) < thr) ? NEG : acc[rb*4+r][cb*4+1] * SCALE;
                v.z = (mv.z != 0 || (j + 2) < thr) ? NEG : acc[rb*4+r][cb*4+2] * SCALE;
                v.w = (mv.w != 0 || (j + 3) < thr) ? NEG : acc[rb*4+r][cb*4+3] * SCALE;
                *(float4*)&orow[j] = v;
            }
        }
}

// ---------------------------------------------------------------------------
// Kernel 2: row softmax in place over the attn region.
// One block (256 threads) per row; each thread owns 8 contiguous elements.
// ---------------------------------------------------------------------------
__device__ __forceinline__ float warpRedMax(float v) {
    #pragma unroll
    for (int o = 16; o > 0; o >>= 1) v = fmaxf(v, __shfl_xor_sync(0xffffffffu, v, o));
    return v;
}
__device__ __forceinline__ float warpRedSum(float v) {
    #pragma unroll
    for (int o = 16; o > 0; o >>= 1) v += __shfl_xor_sync(0xffffffffu, v, o);
    return v;
}

__global__ __launch_bounds__(256) void softmax_kernel(float* __restrict__ attn)
{
    const size_t row = blockIdx.x;
    float* p = attn + row * S_;
    const int tid = threadIdx.x;

    float4 v0 = ((float4*)p)[tid];
    float4 v1 = ((float4*)p)[tid + 256];

    __shared__ float red[8];

    float m = fmaxf(fmaxf(fmaxf(v0.x, v0.y), fmaxf(v0.z, v0.w)),
                    fmaxf(fmaxf(v1.x, v1.y), fmaxf(v1.z, v1.w)));
    m = warpRedMax(m);
    if ((tid & 31) == 0) red[tid >> 5] = m;
    __syncthreads();
    float bm = red[0];
    #pragma unroll
    for (int i = 1; i < 8; ++i) bm = fmaxf(bm, red[i]);
    __syncthreads();

    v0.x = expf(v0.x - bm); v0.y = expf(v0.y - bm);
    v0.z = expf(v0.z - bm); v0.w = expf(v0.w - bm);
    v1.x = expf(v1.x - bm); v1.y = expf(v1.y - bm);
    v1.z = expf(v1.z - bm); v1.w = expf(v1.w - bm);

    float s = (v0.x + v0.y) + (v0.z + v0.w) + (v1.x + v1.y) + (v1.z + v1.w);
    s = warpRedSum(s);
    if ((tid & 31) == 0) red[tid >> 5] = s;
    __syncthreads();
    float bs = 0.0f;
    #pragma unroll
    for (int i = 0; i < 8; ++i) bs += red[i];

    float inv = 1.0f / bs;
    v0.x *= inv; v0.y *= inv; v0.z *= inv; v0.w *= inv;
    v1.x *= inv; v1.y *= inv; v1.z *= inv; v1.w *= inv;

    ((float4*)p)[tid]       = v0;
    ((float4*)p)[tid + 256] = v1;
}

// ---------------------------------------------------------------------------
// Kernel 3: context = attn @ V.
// Tile: 64 (queries) x 128 (DV, full width), k chunked by 32.
// 256 threads, each 4x8 accumulators (columns in 2 quadrants for LDS.128).
// k-tiles entirely inside the window (p == 0 exactly) are skipped.
// ---------------------------------------------------------------------------
__global__ __launch_bounds__(256) void context_kernel(
    const float* __restrict__ attn, const float* __restrict__ V,
    float* __restrict__ ctx)
{
    const int i0 = blockIdx.x * 64;
    const int bh = blockIdx.y;
    const int tid = threadIdx.x;
    const int tx = tid & 15;
    const int ty = tid >> 4;

    __shared__ float Ps[32][68];    // transposed: [k][m]
    __shared__ float Vs[32][132];   // natural:    [k][n]

    float acc[4][8];
    #pragma unroll
    for (int r = 0; r < 4; ++r)
        #pragma unroll
        for (int c = 0; c < 8; ++c) acc[r][c] = 0.0f;

    const float* Pb = attn + ((size_t)bh * S_ + i0) * S_;
    const float* Vb = V + (size_t)bh * S_ * D_;

    const int lk  = tid & 31;
    const int lm  = tid >> 5;
    const int lc4 = (tid & 31) << 2;
    const int vr0 = tid >> 5;

    const int ktStart = ((i0 * 4) / 5) >> 5;   // first key tile that can be nonzero

    for (int kt = ktStart; kt < S_ / 32; ++kt) {
        const int k0 = kt * 32;
        __syncthreads();
        #pragma unroll
        for (int m = lm; m < 64; m += 8)
            Ps[lk][m] = Pb[(size_t)m * S_ + k0 + lk];
        #pragma unroll
        for (int kv = vr0; kv < 32; kv += 8)
            *(float4*)&Vs[kv][lc4] = *(const float4*)&Vb[(size_t)(k0 + kv) * D_ + lc4];
        __syncthreads();

        #pragma unroll
        for (int k = 0; k < 32; ++k) {
            float4 a  = *(const float4*)&Ps[k][ty * 4];
            float4 w0 = *(const float4*)&Vs[k][tx * 4];
            float4 w1 = *(const float4*)&Vs[k][64 + tx * 4];
            float af[4] = {a.x, a.y, a.z, a.w};
            float vf[8] = {w0.x, w0.y, w0.z, w0.w, w1.x, w1.y, w1.z, w1.w};
            #pragma unroll
            for (int r = 0; r < 4; ++r)
                #pragma unroll
                for (int c = 0; c < 8; ++c)
                    acc[r][c] = fmaf(af[r], vf[c], acc[r][c]);
        }
    }

    #pragma unroll
    for (int r = 0; r < 4; ++r) {
        int i = i0 + ty * 4 + r;
        float* crow = ctx + ((size_t)bh * S_ + i) * D_;
        *(float4*)&crow[tx * 4]      = make_float4(acc[r][0], acc[r][1], acc[r][2], acc[r][3]);
        *(float4*)&crow[64 + tx * 4] = make_float4(acc[r][4], acc[r][5], acc[r][6], acc[r][7]);
    }
}

// ---------------------------------------------------------------------------
// kernel_launch — graph-capturable: 3 kernel launches on the default stream,
// no allocation (attn region of d_out doubles as score scratch).
// Output layout: [context (B*H*S*DV floats)] [attn (B*H*S*S floats)]
// ---------------------------------------------------------------------------
extern "C" void kernel_launch(void* const* d_in, const int* in_sizes, int n_in,
                              void* d_out, int out_size)
{
    const float* Q    = (const float*)d_in[0];
    const float* K    = (const float*)d_in[1];
    const float* V    = (const float*)d_in[2];
    const int*   mask = (const int*)d_in[3];

    float* out  = (float*)d_out;
    float* ctx  = out;
    float* attn = out + (size_t)B_ * H_ * S_ * D_;   // 8,388,608 floats offset

    dim3 g1(S_ / 128, S_ / 128, B_ * H_);            // (16, 16, 32)
    scores_kernel<<<g1, 256>>>(Q, K, mask, attn);

    softmax_kernel<<<B_ * H_ * S_, 256>>>(attn);     // 65536 rows

    dim3 g3(S_ / 64, B_ * H_);                       // (32, 32)
    context_kernel<<<g3, 256>>>(attn, V, ctx);

    (void)in_sizes; (void)n_in; (void)out_size;
}

// round 4
// speedup vs baseline: 1.6159x; 1.6159x over previous
#include <cuda_runtime.h>
#include <cuda_bf16.h>
#include <cstdint>

#define B_ 2
#define H_ 16
#define S_ 2048
#define D_ 128
#define SCALE 0.08838834764831845f   // 1/sqrt(128)
#define NEG (-1e9f)

#define TW 136      // smem tile row stride in bf16 elements (128 + 8 pad)
#define SGW 132     // fp32 staging row stride in floats

// Pre-transposed V: Vt[bh][n][k] = V[bh][k][n], split into bf16 hi/lo
__device__ __align__(16) __nv_bfloat16 g_VtHi[(size_t)32 * 128 * 2048];
__device__ __align__(16) __nv_bfloat16 g_VtLo[(size_t)32 * 128 * 2048];

// ---------------------------------------------------------------------------
// Warp MMA: m16n8k16 row.col f32 <- bf16 x bf16 (base sm_80+ feature)
// ---------------------------------------------------------------------------
__device__ __forceinline__ void mma_bf16(float* d,
                                         uint32_t a0, uint32_t a1, uint32_t a2, uint32_t a3,
                                         uint32_t b0, uint32_t b1) {
    asm volatile(
        "mma.sync.aligned.m16n8k16.row.col.f32.bf16.bf16.f32 "
        "{%0,%1,%2,%3}, {%4,%5,%6,%7}, {%8,%9}, {%0,%1,%2,%3};"
        : "+f"(d[0]), "+f"(d[1]), "+f"(d[2]), "+f"(d[3])
        : "r"(a0), "r"(a1), "r"(a2), "r"(a3), "r"(b0), "r"(b1));
}

__device__ __forceinline__ uint32_t pack2(__nv_bfloat16 a, __nv_bfloat16 b) {
    return (uint32_t)__bfloat16_as_ushort(a) | ((uint32_t)__bfloat16_as_ushort(b) << 16);
}

// split fp32x4 -> hi/lo bf16x4, store 8B each (offset in bf16 elements)
__device__ __forceinline__ void store_hilo4(__nv_bfloat16* hi, __nv_bfloat16* lo,
                                            uint32_t off, float4 v) {
    __nv_bfloat16 h0 = __float2bfloat16(v.x), h1 = __float2bfloat16(v.y);
    __nv_bfloat16 h2 = __float2bfloat16(v.z), h3 = __float2bfloat16(v.w);
    __nv_bfloat16 l0 = __float2bfloat16(v.x - __bfloat162float(h0));
    __nv_bfloat16 l1 = __float2bfloat16(v.y - __bfloat162float(h1));
    __nv_bfloat16 l2 = __float2bfloat16(v.z - __bfloat162float(h2));
    __nv_bfloat16 l3 = __float2bfloat16(v.w - __bfloat162float(h3));
    uint2 hp; hp.x = pack2(h0, h1); hp.y = pack2(h2, h3);
    uint2 lp; lp.x = pack2(l0, l1); lp.y = pack2(l2, l3);
    *(uint2*)(hi + off) = hp;
    *(uint2*)(lo + off) = lp;
}

// smem tile region offsets (in bf16 elements), total 4 tiles of 128*TW
#define TILE_ELEMS (128 * TW)
#define SM_BYTES (4 * TILE_ELEMS * 2)

// ---------------------------------------------------------------------------
// K0: V -> Vt (transposed) bf16 hi/lo
// ---------------------------------------------------------------------------
__global__ __launch_bounds__(256) void vt_kernel(const float* __restrict__ V) {
    __shared__ float t[32][33];
    const int k0 = blockIdx.x * 32, n0 = blockIdx.y * 32, bh = blockIdx.z;
    const int tid = threadIdx.x, c = tid & 31, r0 = tid >> 5;
    const float* Vb = V + (size_t)bh * S_ * D_;
    #pragma unroll
    for (int rr = r0; rr < 32; rr += 8)
        t[rr][c] = Vb[(size_t)(k0 + rr) * D_ + n0 + c];
    __syncthreads();
    __nv_bfloat16* Hb = g_VtHi + (size_t)bh * D_ * S_;
    __nv_bfloat16* Lb = g_VtLo + (size_t)bh * D_ * S_;
    #pragma unroll
    for (int rr = r0; rr < 32; rr += 8) {
        float x = t[c][rr];
        __nv_bfloat16 h = __float2bfloat16(x);
        __nv_bfloat16 l = __float2bfloat16(x - __bfloat162float(h));
        size_t o = (size_t)(n0 + rr) * S_ + k0 + c;
        Hb[o] = h;
        Lb[o] = l;
    }
}

// ---------------------------------------------------------------------------
// K1: scores = Q K^T * scale, mask -> attn scratch. 128x128 tile per CTA.
// 8 warps x 16-row stripes; split-bf16 3-MMA per k16 step.
// ---------------------------------------------------------------------------
__global__ __launch_bounds__(256) void scores_mma_kernel(
    const float* __restrict__ Q, const float* __restrict__ K,
    const int* __restrict__ mask, float* __restrict__ attn)
{
    const int bh = blockIdx.z, b = bh >> 4;
    const int i0 = blockIdx.y * 128, j0 = blockIdx.x * 128;
    const int tid = threadIdx.x;
    float* attnBase = attn + ((size_t)bh * S_ + i0) * S_ + j0;

    if (j0 + 128 <= (i0 * 4) / 5) {   // fully below window
        const float4 f = make_float4(NEG, NEG, NEG, NEG);
        for (int idx = tid; idx < 128 * 32; idx += 256)
            *(float4*)&attnBase[(size_t)(idx >> 5) * S_ + ((idx & 31) << 2)] = f;
        return;
    }

    extern __shared__ __nv_bfloat16 sm[];
    __nv_bfloat16* Qhi = sm;
    __nv_bfloat16* Qlo = sm + TILE_ELEMS;
    __nv_bfloat16* Khi = sm + 2 * TILE_ELEMS;
    __nv_bfloat16* Klo = sm + 3 * TILE_ELEMS;

    const float* Qb = Q + ((size_t)bh * S_ + i0) * D_;
    const float* Kb = K + ((size_t)bh * S_ + j0) * D_;

    #pragma unroll
    for (int it = 0; it < 16; ++it) {
        int idx = it * 256 + tid;
        int row = idx >> 5, c4 = (idx & 31) << 2;
        uint32_t off = row * TW + c4;
        store_hilo4(Qhi, Qlo, off, *(const float4*)&Qb[(size_t)row * D_ + c4]);
        store_hilo4(Khi, Klo, off, *(const float4*)&Kb[(size_t)row * D_ + c4]);
    }
    __syncthreads();

    const int lane = tid & 31, warp = tid >> 5;
    const int g = lane >> 2, c = lane & 3;
    const int m0 = warp * 16;

    float acc[16][4];
    #pragma unroll
    for (int nt = 0; nt < 16; ++nt)
        #pragma unroll
        for (int q = 0; q < 4; ++q) acc[nt][q] = 0.0f;

    const uint32_t aoff0 = (m0 + g) * TW + 2 * c;
    const uint32_t aoff1 = (m0 + g + 8) * TW + 2 * c;

    #pragma unroll
    for (int ks = 0; ks < 8; ++ks) {
        const int k0 = ks * 16;
        uint32_t ah0 = *(const uint32_t*)(Qhi + aoff0 + k0);
        uint32_t ah1 = *(const uint32_t*)(Qhi + aoff1 + k0);
        uint32_t ah2 = *(const uint32_t*)(Qhi + aoff0 + k0 + 8);
        uint32_t ah3 = *(const uint32_t*)(Qhi + aoff1 + k0 + 8);
        uint32_t al0 = *(const uint32_t*)(Qlo + aoff0 + k0);
        uint32_t al1 = *(const uint32_t*)(Qlo + aoff1 + k0);
        uint32_t al2 = *(const uint32_t*)(Qlo + aoff0 + k0 + 8);
        uint32_t al3 = *(const uint32_t*)(Qlo + aoff1 + k0 + 8);
        #pragma unroll
        for (int nt = 0; nt < 16; ++nt) {
            uint32_t boff = (nt * 8 + g) * TW + k0 + 2 * c;
            uint32_t bh0 = *(const uint32_t*)(Khi + boff);
            uint32_t bh1 = *(const uint32_t*)(Khi + boff + 8);
            uint32_t bl0 = *(const uint32_t*)(Klo + boff);
            uint32_t bl1 = *(const uint32_t*)(Klo + boff + 8);
            mma_bf16(acc[nt], ah0, ah1, ah2, ah3, bh0, bh1);
            mma_bf16(acc[nt], ah0, ah1, ah2, ah3, bl0, bl1);
            mma_bf16(acc[nt], al0, al1, al2, al3, bh0, bh1);
        }
    }
    __syncthreads();   // everyone done reading Q tiles; reuse as fp32 staging

    float* stg = (float*)sm;
    #pragma unroll
    for (int nt = 0; nt < 16; ++nt) {
        *(float2*)&stg[(m0 + g) * SGW + nt * 8 + 2 * c]     = make_float2(acc[nt][0], acc[nt][1]);
        *(float2*)&stg[(m0 + g + 8) * SGW + nt * 8 + 2 * c] = make_float2(acc[nt][2], acc[nt][3]);
    }
    __syncthreads();

    const int* mB = mask + (size_t)b * S_ * S_;
    #pragma unroll
    for (int it = 0; it < 16; ++it) {
        int idx = it * 256 + tid;
        int r = idx >> 5, cc = (idx & 31) * 4;
        int i = i0 + r, thr = (i * 4) / 5, j = j0 + cc;
        int4 mv = *(const int4*)&mB[(size_t)i * S_ + j];
        float4 s = *(float4*)&stg[r * SGW + cc];
        float4 v;
        v.x = (mv.x || (j + 0) < thr) ? NEG : s.x * SCALE;
        v.y = (mv.y || (j + 1) < thr) ? NEG : s.y * SCALE;
        v.z = (mv.z || (j + 2) < thr) ? NEG : s.z * SCALE;
        v.w = (mv.w || (j + 3) < thr) ? NEG : s.w * SCALE;
        *(float4*)&attnBase[(size_t)r * S_ + cc] = v;
    }
}

// ---------------------------------------------------------------------------
// K2: row softmax in place
// ---------------------------------------------------------------------------
__device__ __forceinline__ float warpRedMax(float v) {
    #pragma unroll
    for (int o = 16; o > 0; o >>= 1) v = fmaxf(v, __shfl_xor_sync(0xffffffffu, v, o));
    return v;
}
__device__ __forceinline__ float warpRedSum(float v) {
    #pragma unroll
    for (int o = 16; o > 0; o >>= 1) v += __shfl_xor_sync(0xffffffffu, v, o);
    return v;
}

__global__ __launch_bounds__(256) void softmax_kernel(float* __restrict__ attn)
{
    const size_t row = blockIdx.x;
    float* p = attn + row * S_;
    const int tid = threadIdx.x;

    float4 v0 = ((float4*)p)[tid];
    float4 v1 = ((float4*)p)[tid + 256];

    __shared__ float red[8];

    float m = fmaxf(fmaxf(fmaxf(v0.x, v0.y), fmaxf(v0.z, v0.w)),
                    fmaxf(fmaxf(v1.x, v1.y), fmaxf(v1.z, v1.w)));
    m = warpRedMax(m);
    if ((tid & 31) == 0) red[tid >> 5] = m;
    __syncthreads();
    float bm = red[0];
    #pragma unroll
    for (int i = 1; i < 8; ++i) bm = fmaxf(bm, red[i]);
    __syncthreads();

    v0.x = expf(v0.x - bm); v0.y = expf(v0.y - bm);
    v0.z = expf(v0.z - bm); v0.w = expf(v0.w - bm);
    v1.x = expf(v1.x - bm); v1.y = expf(v1.y - bm);
    v1.z = expf(v1.z - bm); v1.w = expf(v1.w - bm);

    float s = (v0.x + v0.y) + (v0.z + v0.w) + (v1.x + v1.y) + (v1.z + v1.w);
    s = warpRedSum(s);
    if ((tid & 31) == 0) red[tid >> 5] = s;
    __syncthreads();
    float bs = 0.0f;
    #pragma unroll
    for (int i = 0; i < 8; ++i) bs += red[i];

    float inv = 1.0f / bs;
    v0.x *= inv; v0.y *= inv; v0.z *= inv; v0.w *= inv;
    v1.x *= inv; v1.y *= inv; v1.z *= inv; v1.w *= inv;

    ((float4*)p)[tid]       = v0;
    ((float4*)p)[tid + 256] = v1;
}

// ---------------------------------------------------------------------------
// K3: context = attn @ V. 128x128 output per CTA, loop over key tiles.
// ---------------------------------------------------------------------------
__global__ __launch_bounds__(256) void context_mma_kernel(
    const float* __restrict__ attn, float* __restrict__ ctx)
{
    const int i0 = blockIdx.x * 128, bh = blockIdx.y;
    const int tid = threadIdx.x;

    extern __shared__ __nv_bfloat16 sm[];
    __nv_bfloat16* Phi = sm;
    __nv_bfloat16* Plo = sm + TILE_ELEMS;
    __nv_bfloat16* Vhi = sm + 2 * TILE_ELEMS;
    __nv_bfloat16* Vlo = sm + 3 * TILE_ELEMS;

    const float* Pb = attn + ((size_t)bh * S_ + i0) * S_;
    const __nv_bfloat16* VtH = g_VtHi + (size_t)bh * D_ * S_;
    const __nv_bfloat16* VtL = g_VtLo + (size_t)bh * D_ * S_;

    const int lane = tid & 31, warp = tid >> 5;
    const int g = lane >> 2, c = lane & 3;
    const int m0 = warp * 16;

    float acc[16][4];
    #pragma unroll
    for (int nt = 0; nt < 16; ++nt)
        #pragma unroll
        for (int q = 0; q < 4; ++q) acc[nt][q] = 0.0f;

    const uint32_t aoff0 = (m0 + g) * TW + 2 * c;
    const uint32_t aoff1 = (m0 + g + 8) * TW + 2 * c;

    const int ktStart = ((i0 * 4) / 5) >> 7;

    for (int kt = ktStart; kt < S_ / 128; ++kt) {
        const int k0g = kt * 128;
        __syncthreads();
        // P tile: fp32 -> hi/lo
        #pragma unroll
        for (int it = 0; it < 16; ++it) {
            int idx = it * 256 + tid;
            int row = idx >> 5, c4 = (idx & 31) << 2;
            store_hilo4(Phi, Plo, row * TW + c4,
                        *(const float4*)&Pb[(size_t)row * S_ + k0g + c4]);
        }
        // Vt tiles: already bf16, rows n (contiguous k) -> uint4 = 8 bf16
        #pragma unroll
        for (int it = 0; it < 8; ++it) {
            int idx = it * 256 + tid;
            int n = idx >> 4, k8 = (idx & 15) << 3;
            *(uint4*)(Vhi + n * TW + k8) = *(const uint4*)&VtH[(size_t)n * S_ + k0g + k8];
            *(uint4*)(Vlo + n * TW + k8) = *(const uint4*)&VtL[(size_t)n * S_ + k0g + k8];
        }
        __syncthreads();

        #pragma unroll
        for (int ks = 0; ks < 8; ++ks) {
            const int k0 = ks * 16;
            uint32_t ah0 = *(const uint32_t*)(Phi + aoff0 + k0);
            uint32_t ah1 = *(const uint32_t*)(Phi + aoff1 + k0);
            uint32_t ah2 = *(const uint32_t*)(Phi + aoff0 + k0 + 8);
            uint32_t ah3 = *(const uint32_t*)(Phi + aoff1 + k0 + 8);
            uint32_t al0 = *(const uint32_t*)(Plo + aoff0 + k0);
            uint32_t al1 = *(const uint32_t*)(Plo + aoff1 + k0);
            uint32_t al2 = *(const uint32_t*)(Plo + aoff0 + k0 + 8);
            uint32_t al3 = *(const uint32_t*)(Plo + aoff1 + k0 + 8);
            #pragma unroll
            for (int nt = 0; nt < 16; ++nt) {
                uint32_t boff = (nt * 8 + g) * TW + k0 + 2 * c;
                uint32_t bh0 = *(const uint32_t*)(Vhi + boff);
                uint32_t bh1 = *(const uint32_t*)(Vhi + boff + 8);
                uint32_t bl0 = *(const uint32_t*)(Vlo + boff);
                uint32_t bl1 = *(const uint32_t*)(Vlo + boff + 8);
                mma_bf16(acc[nt], ah0, ah1, ah2, ah3, bh0, bh1);
                mma_bf16(acc[nt], ah0, ah1, ah2, ah3, bl0, bl1);
                mma_bf16(acc[nt], al0, al1, al2, al3, bh0, bh1);
            }
        }
    }
    __syncthreads();

    float* stg = (float*)sm;
    #pragma unroll
    for (int nt = 0; nt < 16; ++nt) {
        *(float2*)&stg[(m0 + g) * SGW + nt * 8 + 2 * c]     = make_float2(acc[nt][0], acc[nt][1]);
        *(float2*)&stg[(m0 + g + 8) * SGW + nt * 8 + 2 * c] = make_float2(acc[nt][2], acc[nt][3]);
    }
    __syncthreads();

    #pragma unroll
    for (int it = 0; it < 16; ++it) {
        int idx = it * 256 + tid;
        int r = idx >> 5, c4 = (idx & 31) << 2;
        *(float4*)&ctx[((size_t)bh * S_ + i0 + r) * D_ + c4] = *(float4*)&stg[r * SGW + c4];
    }
}

// ---------------------------------------------------------------------------
// kernel_launch
// ---------------------------------------------------------------------------
extern "C" void kernel_launch(void* const* d_in, const int* in_sizes, int n_in,
                              void* d_out, int out_size)
{
    const float* Q    = (const float*)d_in[0];
    const float* K    = (const float*)d_in[1];
    const float* V    = (const float*)d_in[2];
    const int*   mask = (const int*)d_in[3];

    float* out  = (float*)d_out;
    float* ctx  = out;
    float* attn = out + (size_t)B_ * H_ * S_ * D_;

    static bool attrs_set = false;
    if (!attrs_set) {
        cudaFuncSetAttribute(scores_mma_kernel, cudaFuncAttributeMaxDynamicSharedMemorySize, SM_BYTES);
        cudaFuncSetAttribute(context_mma_kernel, cudaFuncAttributeMaxDynamicSharedMemorySize, SM_BYTES);
        attrs_set = true;
    }

    vt_kernel<<<dim3(S_ / 32, D_ / 32, B_ * H_), 256>>>(V);

    dim3 g1(S_ / 128, S_ / 128, B_ * H_);
    scores_mma_kernel<<<g1, 256, SM_BYTES>>>(Q, K, mask, attn);

    softmax_kernel<<<B_ * H_ * S_, 256>>>(attn);

    dim3 g3(S_ / 128, B_ * H_);
    context_mma_kernel<<<g3, 256, SM_BYTES>>>(attn, ctx);

    (void)in_sizes; (void)n_in; (void)out_size;
}